// round 2
// baseline (speedup 1.0000x reference)
#include <cuda_runtime.h>
#include <math.h>
#include <stdint.h>

#define H_DIM 1024
#define A_DIM 20
#define K_DIM 4096   // 4*H

// 64 MB scratch for the hidden activations [B, H] (static: no allocation)
__device__ float g_hidden[16384 * 1024];
// valid_mask dtype mode: 0=uint8, 1=int32, 2=float32, 3=bfloat16
__device__ int g_mask_mode;

// ---------------------------------------------------------------------------
// Mask dtype sniffer: looks at the first 64 words of the mask buffer.
// bool arrays only contain {0,1}-valued elements, so the bit patterns are
// unambiguous: 0x3F800000 => f32; 0x3F803F80/0x00003F80 => bf16;
// any word with bytes beyond byte0 set => uint8; else (all words 0/1) => i32.
// ---------------------------------------------------------------------------
__global__ void detect_mask_kernel(const unsigned int* __restrict__ m)
{
    bool f32 = false, bf16 = false, multi = false;
#pragma unroll
    for (int i = 0; i < 64; i++) {
        unsigned int w = m[i];
        if (w == 0x3F800000u) f32 = true;
        else if (w == 0x3F803F80u || w == 0x00003F80u) bf16 = true;
        else if (w > 1u) multi = true;
    }
    int mode;
    if (bf16)      mode = 3;
    else if (f32)  mode = 2;
    else if (multi) mode = 0;
    else           mode = 1;
    g_mask_mode = mode;
}

// ---------------------------------------------------------------------------
// Stage 1: hidden = tanh( concat(x0,x1,x2,x3) @ W1 + b1 )
// M=16384, N=1024, K=4096. 128x128 tile, k-tile 8, 256 threads, 8x8 micro-tile.
// ---------------------------------------------------------------------------
__global__ __launch_bounds__(256, 1) void gemm1_tanh_kernel(
    const float* __restrict__ x0, const float* __restrict__ x1,
    const float* __restrict__ x2, const float* __restrict__ x3,
    const float* __restrict__ W1, const float* __restrict__ b1)
{
    __shared__ float As[2][8][132];
    __shared__ float Bs[2][8][128];

    const int tid = threadIdx.x;
    const int tx = tid & 15;
    const int ty = tid >> 4;
    const int bm = blockIdx.y * 128;
    const int bn = blockIdx.x * 128;

    const int a_row = tid >> 1;
    const int a_kc  = (tid & 1) * 4;
    const long gm   = bm + a_row;

    const int b_kr = tid >> 5;
    const int b_nc = (tid & 31) * 4;

    const float* xs[4] = {x0, x1, x2, x3};

    float acc[8][8];
#pragma unroll
    for (int i = 0; i < 8; i++)
#pragma unroll
        for (int j = 0; j < 8; j++) acc[i][j] = 0.f;

    {
        const int kg = a_kc;
        const float* src = xs[kg >> 10];
        float4 a = *reinterpret_cast<const float4*>(&src[gm * 1024 + (kg & 1023)]);
        As[0][a_kc + 0][a_row] = a.x;
        As[0][a_kc + 1][a_row] = a.y;
        As[0][a_kc + 2][a_row] = a.z;
        As[0][a_kc + 3][a_row] = a.w;
        float4 b = *reinterpret_cast<const float4*>(&W1[(long)b_kr * 1024 + bn + b_nc]);
        *reinterpret_cast<float4*>(&Bs[0][b_kr][b_nc]) = b;
    }
    __syncthreads();

    const int KT = K_DIM / 8;
    int buf = 0;
    for (int t = 0; t < KT; ++t) {
        const int nbuf = buf ^ 1;
        float4 pa, pb;
        const bool have_next = (t + 1 < KT);
        if (have_next) {
            const int k0 = (t + 1) * 8;
            const int kg = k0 + a_kc;
            const float* src = xs[kg >> 10];
            pa = *reinterpret_cast<const float4*>(&src[gm * 1024 + (kg & 1023)]);
            pb = *reinterpret_cast<const float4*>(&W1[(long)(k0 + b_kr) * 1024 + bn + b_nc]);
        }

#pragma unroll
        for (int k = 0; k < 8; ++k) {
            float4 a0  = *reinterpret_cast<const float4*>(&As[buf][k][ty * 8]);
            float4 a1  = *reinterpret_cast<const float4*>(&As[buf][k][ty * 8 + 4]);
            float4 b0  = *reinterpret_cast<const float4*>(&Bs[buf][k][tx * 8]);
            float4 b1v = *reinterpret_cast<const float4*>(&Bs[buf][k][tx * 8 + 4]);
            float am[8] = {a0.x, a0.y, a0.z, a0.w, a1.x, a1.y, a1.z, a1.w};
            float bv[8] = {b0.x, b0.y, b0.z, b0.w, b1v.x, b1v.y, b1v.z, b1v.w};
#pragma unroll
            for (int i = 0; i < 8; i++)
#pragma unroll
                for (int j = 0; j < 8; j++)
                    acc[i][j] = fmaf(am[i], bv[j], acc[i][j]);
        }

        if (have_next) {
            As[nbuf][a_kc + 0][a_row] = pa.x;
            As[nbuf][a_kc + 1][a_row] = pa.y;
            As[nbuf][a_kc + 2][a_row] = pa.z;
            As[nbuf][a_kc + 3][a_row] = pa.w;
            *reinterpret_cast<float4*>(&Bs[nbuf][b_kr][b_nc]) = pb;
        }
        __syncthreads();
        buf = nbuf;
    }

    const int gn0 = bn + tx * 8;
    float bb[8];
#pragma unroll
    for (int j = 0; j < 8; j++) bb[j] = __ldg(&b1[gn0 + j]);

#pragma unroll
    for (int i = 0; i < 8; i++) {
        const long row = bm + ty * 8 + i;
        float4 o0, o1;
        o0.x = tanhf(acc[i][0] + bb[0]);
        o0.y = tanhf(acc[i][1] + bb[1]);
        o0.z = tanhf(acc[i][2] + bb[2]);
        o0.w = tanhf(acc[i][3] + bb[3]);
        o1.x = tanhf(acc[i][4] + bb[4]);
        o1.y = tanhf(acc[i][5] + bb[5]);
        o1.z = tanhf(acc[i][6] + bb[6]);
        o1.w = tanhf(acc[i][7] + bb[7]);
        *reinterpret_cast<float4*>(&g_hidden[row * 1024 + gn0])     = o0;
        *reinterpret_cast<float4*>(&g_hidden[row * 1024 + gn0 + 4]) = o1;
    }
}

// ---------------------------------------------------------------------------
// Stage 2: logits = hidden @ W2 + b2; masked log_softmax; argmax + gather.
// One warp per row; W2 transposed into SMEM.
// ---------------------------------------------------------------------------
__global__ __launch_bounds__(256) void stage2_kernel(
    const float* __restrict__ W2, const float* __restrict__ b2,
    const void* __restrict__ valid_mask,
    const int* __restrict__ real_actions,
    float* __restrict__ out, int B, int write_pred)
{
    extern __shared__ float W2t[];  // [20][1024]
    for (int i = threadIdx.x; i < A_DIM * H_DIM; i += blockDim.x) {
        const int a = i >> 10;
        const int k = i & 1023;
        W2t[a * H_DIM + k] = W2[k * A_DIM + a];
    }
    __syncthreads();

    const int warp = threadIdx.x >> 5;
    const int lane = threadIdx.x & 31;
    const int row  = blockIdx.x * 8 + warp;
    if (row >= B) return;

    float acc[A_DIM];
#pragma unroll
    for (int a = 0; a < A_DIM; a++) acc[a] = 0.f;

    const float* hrow = g_hidden + (long)row * H_DIM;
    for (int j = 0; j < H_DIM / 32; j++) {
        const int k = lane + 32 * j;
        const float h = hrow[k];
#pragma unroll
        for (int a = 0; a < A_DIM; a++)
            acc[a] = fmaf(h, W2t[a * H_DIM + k], acc[a]);
    }

#pragma unroll
    for (int off = 16; off > 0; off >>= 1)
#pragma unroll
        for (int a = 0; a < A_DIM; a++)
            acc[a] += __shfl_xor_sync(0xffffffffu, acc[a], off);

    if (lane == 0) {
        const int mode = g_mask_mode;
        const long base = (long)row * A_DIM;
        float masked[A_DIM];
        float m = -3.0e38f;
#pragma unroll
        for (int a = 0; a < A_DIM; a++) {
            const float l = acc[a] + b2[a];
            bool valid;
            if (mode == 1)
                valid = ((const int*)valid_mask)[base + a] != 0;
            else if (mode == 2)
                valid = ((const float*)valid_mask)[base + a] != 0.0f;
            else if (mode == 0)
                valid = ((const unsigned char*)valid_mask)[base + a] != 0;
            else
                valid = ((const unsigned short*)valid_mask)[base + a] != 0;
            masked[a] = valid ? l : -1e9f;
            m = fmaxf(m, masked[a]);
        }
        float s = 0.f;
#pragma unroll
        for (int a = 0; a < A_DIM; a++) s += expf(masked[a] - m);
        const float lse = m + logf(s);

        int pred = 0;
        float best = masked[0];
#pragma unroll
        for (int a = 1; a < A_DIM; a++) {
            if (masked[a] > best) { best = masked[a]; pred = a; }
        }
        const int gold = real_actions[row];
        const float loss = masked[gold] - lse;

        if (write_pred) {
            out[row]     = (float)pred;
            out[B + row] = loss;
        } else {
            out[row] = loss;
        }
    }
}

// ---------------------------------------------------------------------------
extern "C" void kernel_launch(void* const* d_in, const int* in_sizes, int n_in,
                              void* d_out, int out_size)
{
    const float* buffer_h = (const float*)d_in[0];
    const float* stack_h  = (const float*)d_in[1];
    const float* output_h = (const float*)d_in[2];
    const float* action_h = (const float*)d_in[3];
    const float* W1 = (const float*)d_in[4];
    const float* b1 = (const float*)d_in[5];
    const float* W2 = (const float*)d_in[6];
    const float* b2 = (const float*)d_in[7];
    const void* valid_mask = d_in[8];
    const int* real_actions = (const int*)d_in[9];
    float* out = (float*)d_out;

    const int B = in_sizes[0] / H_DIM;  // 16384

    detect_mask_kernel<<<1, 1>>>((const unsigned int*)valid_mask);

    dim3 grid1(H_DIM / 128, B / 128);
    gemm1_tanh_kernel<<<grid1, 256>>>(buffer_h, stack_h, output_h, action_h, W1, b1);

    static const size_t smem2 = (size_t)A_DIM * H_DIM * sizeof(float);
    cudaFuncSetAttribute(stage2_kernel,
                         cudaFuncAttributeMaxDynamicSharedMemorySize, (int)smem2);
    const int write_pred = (out_size >= 2 * B) ? 1 : 0;
    dim3 grid2((B + 7) / 8);
    stage2_kernel<<<grid2, 256, smem2>>>(W2, b2, valid_mask, real_actions,
                                         out, B, write_pred);
}

// round 4
// speedup vs baseline: 1.2989x; 1.2989x over previous
#include <cuda_runtime.h>
#include <math.h>
#include <stdint.h>

#define BDIM  16384
#define H_DIM 1024
#define A_DIM 20
#define K_DIM 4096

#define BM 128
#define BN 128
#define BK 32
#define NSTAGE (K_DIM / BK)      // 128
#define APAD 36                  // smem row stride in floats (conflict-free frags)
#define BUF_FLOATS (128 * APAD)  // 4608 floats = 18432 B per tile buffer

// Static scratch (no allocations allowed)
__device__ __align__(1024) float g_hidden[(size_t)BDIM * H_DIM];   // 64 MB
__device__ __align__(1024) float g_Bt[(size_t)H_DIM * K_DIM];     // 16 MB: W1^T [n][k]

// ---------------------------------------------------------------- helpers --
__device__ __forceinline__ uint32_t smem_u32(const void* p) {
    uint32_t a;
    asm("{ .reg .u64 t; cvta.to.shared.u64 t, %1; cvt.u32.u64 %0, t; }"
        : "=r"(a) : "l"(p));
    return a;
}
__device__ __forceinline__ void cp_async16(uint32_t dst, const void* src) {
    asm volatile("cp.async.cg.shared.global [%0], [%1], 16;" :: "r"(dst), "l"(src));
}
__device__ __forceinline__ void split_tf32(float x, uint32_t& hi, uint32_t& lo) {
    asm("cvt.rna.tf32.f32 %0, %1;" : "=r"(hi) : "f"(x));
    lo = __float_as_uint(x - __uint_as_float(hi));
}
__device__ __forceinline__ void mma_tf32(float* c, const uint32_t* a, const uint32_t* b) {
    asm volatile(
        "mma.sync.aligned.m16n8k8.row.col.f32.tf32.tf32.f32 "
        "{%0,%1,%2,%3},{%4,%5,%6,%7},{%8,%9},{%0,%1,%2,%3};"
        : "+f"(c[0]), "+f"(c[1]), "+f"(c[2]), "+f"(c[3])
        : "r"(a[0]), "r"(a[1]), "r"(a[2]), "r"(a[3]), "r"(b[0]), "r"(b[1]));
}

// -------------------------------------------------- pre-pass: W1 transpose --
__global__ void transposeW1_kernel(const float* __restrict__ W1)
{
    __shared__ float tile[32][33];
    const int k0 = blockIdx.y * 32;
    const int n0 = blockIdx.x * 32;
    const int tx = threadIdx.x, ty = threadIdx.y;
#pragma unroll
    for (int j = 0; j < 32; j += 8)
        tile[ty + j][tx] = W1[(size_t)(k0 + ty + j) * H_DIM + n0 + tx];
    __syncthreads();
#pragma unroll
    for (int j = 0; j < 32; j += 8)
        g_Bt[(size_t)(n0 + ty + j) * K_DIM + k0 + tx] = tile[tx][ty + j];
}

// ----------------------------------------- stage 1: mma.sync tf32x3 GEMM ---
// hidden = tanh(concat(x0..x3) @ W1 + b1), A row-major [B,4096], Bt [1024,4096]
__global__ __launch_bounds__(256, 2) void gemm1_mma_kernel(
    const float* __restrict__ x0, const float* __restrict__ x1,
    const float* __restrict__ x2, const float* __restrict__ x3,
    const float* __restrict__ b1)
{
    extern __shared__ float smem[];
    float* As = smem;                     // [2][128][36]
    float* Bs = smem + 2 * BUF_FLOATS;    // [2][128][36]
    const uint32_t sAs = smem_u32(As);
    const uint32_t sBs = smem_u32(Bs);

    const int tid  = threadIdx.x;
    const int wid  = tid >> 5;
    const int lane = tid & 31;
    const int wm = wid >> 1;              // 0..3
    const int wn = wid & 1;               // 0..1
    const int g  = lane >> 2;             // 0..7
    const int tq = lane & 3;              // 0..3

    const int bm = blockIdx.y * BM;
    const int bn = blockIdx.x * BN;

    const float* xs[4] = {x0, x1, x2, x3};

    // loader: per stage, A = 1024 16B chunks, B = 1024 chunks; 4+4 per thread
    const int lr = tid >> 1;                    // 0..127 (two threads per row)
    const int lc4 = (tid & 1) * 4;              // chunk col 0 or 4
    auto load_stage = [&](int t) {
        const int b = t & 1;
        const int k0 = t * BK;
#pragma unroll
        for (int cc = 0; cc < 4; cc++) {
            const int c = lc4 + cc;             // 0..7
            const int kg = k0 + c * 4;
            // A row lr: concat source select
            const float* src = xs[kg >> 10];
            cp_async16(sAs + (uint32_t)(b * BUF_FLOATS + lr * APAD + c * 4) * 4,
                       src + (size_t)(bm + lr) * H_DIM + (kg & 1023));
            cp_async16(sBs + (uint32_t)(b * BUF_FLOATS + lr * APAD + c * 4) * 4,
                       g_Bt + (size_t)(bn + lr) * K_DIM + kg);
        }
        asm volatile("cp.async.commit_group;" ::: "memory");
    };

    float acc[2][8][4];
#pragma unroll
    for (int i = 0; i < 2; i++)
#pragma unroll
        for (int j = 0; j < 8; j++)
#pragma unroll
            for (int q = 0; q < 4; q++) acc[i][j][q] = 0.f;

    load_stage(0);
    load_stage(1);
    asm volatile("cp.async.wait_group 1;" ::: "memory");
    __syncthreads();

    const int aRowBase = wm * 32 + g;
    const int bRowBase = wn * 64 + g;

    for (int t = 0; t < NSTAGE; ++t) {
        const int buf = t & 1;
        const float* Ab = As + buf * BUF_FLOATS;
        const float* Bb = Bs + buf * BUF_FLOATS;

#pragma unroll
        for (int ks = 0; ks < 4; ks++) {
            const int kc = ks * 8 + tq;
            uint32_t ah[2][4], al[2][4];
#pragma unroll
            for (int i = 0; i < 2; i++) {
                const int r0 = (aRowBase + i * 16) * APAD;
                const int r1 = r0 + 8 * APAD;
                split_tf32(Ab[r0 + kc],     ah[i][0], al[i][0]);
                split_tf32(Ab[r1 + kc],     ah[i][1], al[i][1]);
                split_tf32(Ab[r0 + kc + 4], ah[i][2], al[i][2]);
                split_tf32(Ab[r1 + kc + 4], ah[i][3], al[i][3]);
            }
#pragma unroll
            for (int j = 0; j < 8; j++) {
                const int br = (bRowBase + j * 8) * APAD;
                uint32_t bh[2], bl[2];
                split_tf32(Bb[br + kc],     bh[0], bl[0]);
                split_tf32(Bb[br + kc + 4], bh[1], bl[1]);
#pragma unroll
                for (int i = 0; i < 2; i++) {
                    mma_tf32(acc[i][j], ah[i], bh);
                    mma_tf32(acc[i][j], al[i], bh);
                    mma_tf32(acc[i][j], ah[i], bl);
                }
            }
        }

        __syncthreads();                       // all warps done with buf t
        if (t + 2 < NSTAGE) {
            load_stage(t + 2);
            asm volatile("cp.async.wait_group 1;" ::: "memory");
        } else {
            asm volatile("cp.async.wait_group 0;" ::: "memory");
        }
        __syncthreads();                       // stage t+1 visible
    }

    // epilogue: +b1, tanh, store
#pragma unroll
    for (int j = 0; j < 8; j++) {
        const int col = bn + wn * 64 + j * 8 + 2 * tq;
        const float bb0 = __ldg(&b1[col]);
        const float bb1 = __ldg(&b1[col + 1]);
#pragma unroll
        for (int i = 0; i < 2; i++) {
            const int row0 = bm + wm * 32 + i * 16 + g;
            float2 v0, v1;
            v0.x = tanhf(acc[i][j][0] + bb0);
            v0.y = tanhf(acc[i][j][1] + bb1);
            v1.x = tanhf(acc[i][j][2] + bb0);
            v1.y = tanhf(acc[i][j][3] + bb1);
            *(float2*)(g_hidden + (size_t)row0 * H_DIM + col)       = v0;
            *(float2*)(g_hidden + (size_t)(row0 + 8) * H_DIM + col) = v1;
        }
    }
}

// -------------------------------------------------------------- stage 2 ---
__global__ __launch_bounds__(256) void stage2_kernel(
    const float* __restrict__ W2, const float* __restrict__ b2,
    const void* __restrict__ valid_mask,
    const int* __restrict__ real_actions,
    float* __restrict__ out, int B, int write_pred)
{
    extern __shared__ float W2t[];  // [20][1024]
    __shared__ int s_mode;
    if (threadIdx.x == 0) {
        const unsigned int* m = (const unsigned int*)valid_mask;
        bool f32 = false, bf16 = false, multi = false;
#pragma unroll
        for (int i = 0; i < 64; i++) {
            unsigned int w = m[i];
            if (w == 0x3F800000u) f32 = true;
            else if (w == 0x3F803F80u || w == 0x00003F80u) bf16 = true;
            else if (w > 1u) multi = true;
        }
        s_mode = bf16 ? 3 : f32 ? 2 : multi ? 0 : 1;
    }
    for (int i = threadIdx.x; i < A_DIM * H_DIM; i += blockDim.x) {
        const int a = i >> 10;
        const int k = i & 1023;
        W2t[a * H_DIM + k] = W2[k * A_DIM + a];
    }
    __syncthreads();

    const int warp = threadIdx.x >> 5;
    const int lane = threadIdx.x & 31;
    const int row  = blockIdx.x * 8 + warp;
    if (row >= B) return;

    float acc[A_DIM];
#pragma unroll
    for (int a = 0; a < A_DIM; a++) acc[a] = 0.f;

    const float* hrow = g_hidden + (size_t)row * H_DIM;
    for (int j = 0; j < H_DIM / 32; j++) {
        const int k = lane + 32 * j;
        const float h = hrow[k];
#pragma unroll
        for (int a = 0; a < A_DIM; a++)
            acc[a] = fmaf(h, W2t[a * H_DIM + k], acc[a]);
    }

#pragma unroll
    for (int off = 16; off > 0; off >>= 1)
#pragma unroll
        for (int a = 0; a < A_DIM; a++)
            acc[a] += __shfl_xor_sync(0xffffffffu, acc[a], off);

    if (lane == 0) {
        const int mode = s_mode;
        const long base = (long)row * A_DIM;
        float masked[A_DIM];
        float m = -3.0e38f;
#pragma unroll
        for (int a = 0; a < A_DIM; a++) {
            const float l = acc[a] + b2[a];
            bool valid;
            if (mode == 1)      valid = ((const int*)valid_mask)[base + a] != 0;
            else if (mode == 2) valid = ((const float*)valid_mask)[base + a] != 0.0f;
            else if (mode == 0) valid = ((const unsigned char*)valid_mask)[base + a] != 0;
            else                valid = ((const unsigned short*)valid_mask)[base + a] != 0;
            masked[a] = valid ? l : -1e9f;
            m = fmaxf(m, masked[a]);
        }
        float s = 0.f;
#pragma unroll
        for (int a = 0; a < A_DIM; a++) s += expf(masked[a] - m);
        const float lse = m + logf(s);

        int pred = 0;
        float best = masked[0];
#pragma unroll
        for (int a = 1; a < A_DIM; a++)
            if (masked[a] > best) { best = masked[a]; pred = a; }

        const int gold = real_actions[row];
        const float loss = masked[gold] - lse;

        if (write_pred) {
            out[row]     = (float)pred;
            out[B + row] = loss;
        } else {
            out[row] = loss;
        }
    }
}

// ---------------------------------------------------------------- launch --
extern "C" void kernel_launch(void* const* d_in, const int* in_sizes, int n_in,
                              void* d_out, int out_size)
{
    const float* buffer_h = (const float*)d_in[0];
    const float* stack_h  = (const float*)d_in[1];
    const float* output_h = (const float*)d_in[2];
    const float* action_h = (const float*)d_in[3];
    const float* W1 = (const float*)d_in[4];
    const float* b1 = (const float*)d_in[5];
    const float* W2 = (const float*)d_in[6];
    const float* b2 = (const float*)d_in[7];
    const void* valid_mask = d_in[8];
    const int* real_actions = (const int*)d_in[9];
    float* out = (float*)d_out;

    const int B = in_sizes[0] / H_DIM;  // 16384

    transposeW1_kernel<<<dim3(H_DIM / 32, K_DIM / 32), dim3(32, 8)>>>(W1);

    const int smem1 = 4 * BUF_FLOATS * sizeof(float);  // 73728
    cudaFuncSetAttribute(gemm1_mma_kernel,
                         cudaFuncAttributeMaxDynamicSharedMemorySize, smem1);
    dim3 grid1(H_DIM / BN, B / BM);   // (8, 128)
    gemm1_mma_kernel<<<grid1, 256, smem1>>>(buffer_h, stack_h, output_h,
                                            action_h, b1);

    static const size_t smem2 = (size_t)A_DIM * H_DIM * sizeof(float);
    cudaFuncSetAttribute(stage2_kernel,
                         cudaFuncAttributeMaxDynamicSharedMemorySize, (int)smem2);
    const int write_pred = (out_size >= 2 * B) ? 1 : 0;
    dim3 grid2((B + 7) / 8);
    stage2_kernel<<<grid2, 256, smem2>>>(W2, b2, valid_mask, real_actions,
                                         out, B, write_pred);
}

// round 5
// speedup vs baseline: 2.4247x; 1.8667x over previous
#include <cuda_runtime.h>
#include <cuda_fp16.h>
#include <math.h>
#include <stdint.h>

#define BDIM  16384
#define H_DIM 1024
#define A_DIM 20
#define K_DIM 4096

#define BM 128
#define BN 256
#define BK 64
#define NSTAGE (K_DIM / BK)      // 64
#define STAGEB 98304             // 96 KB per stage buffer
#define W_SCALE 2048.0f
#define INV_W_SCALE (1.0f / 2048.0f)

// Static scratch (no allocations allowed)
__device__ __align__(1024) float  g_hidden[(size_t)BDIM * H_DIM];  // 64 MB
__device__ __align__(1024) __half g_Ahi[(size_t)BDIM * K_DIM];     // 128 MB
__device__ __align__(1024) __half g_Alo[(size_t)BDIM * K_DIM];     // 128 MB
__device__ __align__(1024) __half g_Bhi[(size_t)H_DIM * K_DIM];    // 8 MB (2048*W1^T hi)
__device__ __align__(1024) __half g_Blo[(size_t)H_DIM * K_DIM];    // 8 MB

// ---------------------------------------------------------------- helpers --
__device__ __forceinline__ uint32_t smem_u32(const void* p) {
    uint32_t a;
    asm("{ .reg .u64 t; cvta.to.shared.u64 t, %1; cvt.u32.u64 %0, t; }"
        : "=r"(a) : "l"(p));
    return a;
}
__device__ __forceinline__ void cp_async16(uint32_t dst, const void* src) {
    asm volatile("cp.async.cg.shared.global [%0], [%1], 16;" :: "r"(dst), "l"(src));
}
#define SW128(o) ((o) ^ (((o) >> 3) & 0x70))

#define LDSM4(r, addr) \
    asm volatile("ldmatrix.sync.aligned.m8n8.x4.shared.b16 {%0,%1,%2,%3}, [%4];" \
        : "=r"((r)[0]), "=r"((r)[1]), "=r"((r)[2]), "=r"((r)[3]) : "r"(addr))

__device__ __forceinline__ void mma_f16(float* c, const uint32_t* a, const uint32_t* b) {
    asm volatile(
        "mma.sync.aligned.m16n8k16.row.col.f32.f16.f16.f32 "
        "{%0,%1,%2,%3},{%4,%5,%6,%7},{%8,%9},{%0,%1,%2,%3};"
        : "+f"(c[0]), "+f"(c[1]), "+f"(c[2]), "+f"(c[3])
        : "r"(a[0]), "r"(a[1]), "r"(a[2]), "r"(a[3]), "r"(b[0]), "r"(b[1]));
}

// ------------------------------------------------------------- pre-passes --
// Split concat(x0..x3) into fp16 hi/lo planes [B, 4096]
__global__ __launch_bounds__(256) void splitA_kernel(
    const float* __restrict__ x0, const float* __restrict__ x1,
    const float* __restrict__ x2, const float* __restrict__ x3)
{
    const size_t i = (size_t)blockIdx.x * blockDim.x + threadIdx.x;  // float4 idx
    if (i >= (size_t)BDIM * K_DIM / 4) return;
    const size_t m = i >> 10;
    const int kq = (int)(i & 1023);
    const int part = kq >> 8;
    const int kin = (kq & 255) * 4;
    const float* xs = part == 0 ? x0 : part == 1 ? x1 : part == 2 ? x2 : x3;
    float4 a = *(const float4*)(xs + m * H_DIM + kin);

    __half h0 = __float2half_rn(a.x), h1 = __float2half_rn(a.y);
    __half h2 = __float2half_rn(a.z), h3 = __float2half_rn(a.w);
    __half l0 = __float2half_rn(a.x - __half2float(h0));
    __half l1 = __float2half_rn(a.y - __half2float(h1));
    __half l2 = __float2half_rn(a.z - __half2float(h2));
    __half l3 = __float2half_rn(a.w - __half2float(h3));

    __half2* ph = (__half2*)(g_Ahi + i * 4);
    __half2* pl = (__half2*)(g_Alo + i * 4);
    ph[0] = __halves2half2(h0, h1); ph[1] = __halves2half2(h2, h3);
    pl[0] = __halves2half2(l0, l1); pl[1] = __halves2half2(l2, l3);
}

// Transpose W1 [4096,1024] -> [1024,4096], scale by 2048, split fp16 hi/lo
__global__ void splitB_kernel(const float* __restrict__ W1)
{
    __shared__ float tile[32][33];
    const int k0 = blockIdx.y * 32;
    const int n0 = blockIdx.x * 32;
    const int tx = threadIdx.x, ty = threadIdx.y;
#pragma unroll
    for (int j = 0; j < 32; j += 8)
        tile[ty + j][tx] = W1[(size_t)(k0 + ty + j) * H_DIM + n0 + tx];
    __syncthreads();
#pragma unroll
    for (int j = 0; j < 32; j += 8) {
        const int n = n0 + ty + j, k = k0 + tx;
        const float v = tile[tx][ty + j] * W_SCALE;
        const __half h = __float2half_rn(v);
        g_Bhi[(size_t)n * K_DIM + k] = h;
        g_Blo[(size_t)n * K_DIM + k] = __float2half_rn(v - __half2float(h));
    }
}

// ------------------------------------------- stage 1: fp16x3 mma GEMM ------
// hidden = tanh((Ahi+Alo) @ (Bhi+Blo)^T / 2048 + b1), drop lo*lo term.
// smem per stage: Ahi 16K | Alo 16K | Bhi 32K | Blo 32K  (rows = 128B, SW128)
__global__ __launch_bounds__(512, 1) void gemm1_fp16_kernel(const float* __restrict__ b1)
{
    extern __shared__ char smem[];
    const uint32_t sb = smem_u32(smem);
    const int tid  = threadIdx.x;
    const int wid  = tid >> 5;
    const int lane = tid & 31;
    const int wm = wid & 3;     // 4 m-tiles of 32
    const int wn = wid >> 2;    // 4 n-tiles of 64
    const int bm = blockIdx.y * BM;
    const int bn = blockIdx.x * BN;

    auto load_stage = [&](int t) {
        const int st = t & 1;
        const int k0 = t * BK;
        const uint32_t base = sb + st * STAGEB;
#pragma unroll
        for (int c = 0; c < 4; c++) {                 // A: 2048 chunks
            const int idx = c * 512 + tid;
            const int plane = idx >> 10, rem = idx & 1023;
            const int r = rem >> 3, seg = rem & 7;
            const __half* gp = plane ? g_Alo : g_Ahi;
            cp_async16(base + plane * 16384 + SW128((uint32_t)(r * 128 + seg * 16)),
                       gp + (size_t)(bm + r) * K_DIM + k0 + seg * 8);
        }
#pragma unroll
        for (int c = 0; c < 8; c++) {                 // B: 4096 chunks
            const int idx = c * 512 + tid;
            const int plane = idx >> 11, rem = idx & 2047;
            const int r = rem >> 3, seg = rem & 7;
            const __half* gp = plane ? g_Blo : g_Bhi;
            cp_async16(base + 32768 + plane * 32768 + SW128((uint32_t)(r * 128 + seg * 16)),
                       gp + (size_t)(bn + r) * K_DIM + k0 + seg * 8);
        }
        asm volatile("cp.async.commit_group;" ::: "memory");
    };

    float acc[2][8][4];
#pragma unroll
    for (int i = 0; i < 2; i++)
#pragma unroll
        for (int j = 0; j < 8; j++)
#pragma unroll
            for (int q = 0; q < 4; q++) acc[i][j][q] = 0.f;

    load_stage(0);
    load_stage(1);
    asm volatile("cp.async.wait_group 1;" ::: "memory");
    __syncthreads();

    // ldmatrix lane addressing
    const int rA = wm * 32 + (lane & 15);        // + i*16
    const int rB0 = wn * 64 + (lane & 15);       // + p*16
    const int sseg = lane >> 4;                  // 0/1: which 16B within k16

    for (int t = 0; t < NSTAGE; ++t) {
        const uint32_t base = sb + (t & 1) * STAGEB;
#pragma unroll
        for (int ks = 0; ks < 4; ks++) {
            uint32_t ah[2][4], al[2][4];
#pragma unroll
            for (int i = 0; i < 2; i++) {
                const int r = rA + i * 16;
                const uint32_t addr = base + (uint32_t)(r * 128)
                                    + ((uint32_t)((ks * 2 + sseg) ^ (r & 7)) << 4);
                LDSM4(ah[i], addr);
                LDSM4(al[i], addr + 16384);
            }
            uint32_t bb[4][4];
#pragma unroll
            for (int p = 0; p < 4; p++) {
                const int r = rB0 + p * 16;
                const uint32_t addr = base + 32768 + (uint32_t)(r * 128)
                                    + ((uint32_t)((ks * 2 + sseg) ^ (r & 7)) << 4);
                LDSM4(bb[p], addr);
            }
            // hi*hi and lo*hi
#pragma unroll
            for (int j = 0; j < 8; j++) {
                uint32_t bf[2] = { bb[j >> 1][j & 1], bb[j >> 1][(j & 1) + 2] };
                mma_f16(acc[0][j], ah[0], bf);
                mma_f16(acc[1][j], ah[1], bf);
                mma_f16(acc[0][j], al[0], bf);
                mma_f16(acc[1][j], al[1], bf);
            }
            // hi*lo
#pragma unroll
            for (int p = 0; p < 4; p++) {
                const int r = rB0 + p * 16;
                const uint32_t addr = base + 65536 + (uint32_t)(r * 128)
                                    + ((uint32_t)((ks * 2 + sseg) ^ (r & 7)) << 4);
                LDSM4(bb[p], addr);
            }
#pragma unroll
            for (int j = 0; j < 8; j++) {
                uint32_t bf[2] = { bb[j >> 1][j & 1], bb[j >> 1][(j & 1) + 2] };
                mma_f16(acc[0][j], ah[0], bf);
                mma_f16(acc[1][j], ah[1], bf);
            }
        }
        __syncthreads();
        if (t + 2 < NSTAGE) {
            load_stage(t + 2);
            asm volatile("cp.async.wait_group 1;" ::: "memory");
        } else {
            asm volatile("cp.async.wait_group 0;" ::: "memory");
        }
        __syncthreads();
    }

    // epilogue: scale back, +b1, tanh
    const int g  = lane >> 2;
    const int tq = lane & 3;
#pragma unroll
    for (int j = 0; j < 8; j++) {
        const int col = bn + wn * 64 + j * 8 + tq * 2;
        const float bb0 = __ldg(&b1[col]);
        const float bb1 = __ldg(&b1[col + 1]);
#pragma unroll
        for (int i = 0; i < 2; i++) {
            const int row0 = bm + wm * 32 + i * 16 + g;
            float2 v0, v1;
            v0.x = tanhf(fmaf(acc[i][j][0], INV_W_SCALE, bb0));
            v0.y = tanhf(fmaf(acc[i][j][1], INV_W_SCALE, bb1));
            v1.x = tanhf(fmaf(acc[i][j][2], INV_W_SCALE, bb0));
            v1.y = tanhf(fmaf(acc[i][j][3], INV_W_SCALE, bb1));
            *(float2*)(g_hidden + (size_t)row0 * H_DIM + col)       = v0;
            *(float2*)(g_hidden + (size_t)(row0 + 8) * H_DIM + col) = v1;
        }
    }
}

// -------------------------------------------------------------- stage 2 ---
__global__ __launch_bounds__(256) void stage2_kernel(
    const float* __restrict__ W2, const float* __restrict__ b2,
    const void* __restrict__ valid_mask,
    const int* __restrict__ real_actions,
    float* __restrict__ out, int B, int write_pred)
{
    extern __shared__ float W2t[];  // [20][1024]
    __shared__ int s_mode;
    if (threadIdx.x == 0) {
        const unsigned int* m = (const unsigned int*)valid_mask;
        bool f32 = false, bf16 = false, multi = false;
#pragma unroll
        for (int i = 0; i < 64; i++) {
            unsigned int w = m[i];
            if (w == 0x3F800000u) f32 = true;
            else if (w == 0x3F803F80u || w == 0x00003F80u) bf16 = true;
            else if (w > 1u) multi = true;
        }
        s_mode = bf16 ? 3 : f32 ? 2 : multi ? 0 : 1;
    }
    for (int i = threadIdx.x; i < A_DIM * H_DIM; i += blockDim.x) {
        const int a = i >> 10;
        const int k = i & 1023;
        W2t[a * H_DIM + k] = W2[k * A_DIM + a];
    }
    __syncthreads();

    const int warp = threadIdx.x >> 5;
    const int lane = threadIdx.x & 31;
    const int row  = blockIdx.x * 8 + warp;
    if (row >= B) return;

    float acc[A_DIM];
#pragma unroll
    for (int a = 0; a < A_DIM; a++) acc[a] = 0.f;

    const float* hrow = g_hidden + (size_t)row * H_DIM;
    for (int j = 0; j < H_DIM / 32; j++) {
        const int k = lane + 32 * j;
        const float h = hrow[k];
#pragma unroll
        for (int a = 0; a < A_DIM; a++)
            acc[a] = fmaf(h, W2t[a * H_DIM + k], acc[a]);
    }

#pragma unroll
    for (int off = 16; off > 0; off >>= 1)
#pragma unroll
        for (int a = 0; a < A_DIM; a++)
            acc[a] += __shfl_xor_sync(0xffffffffu, acc[a], off);

    if (lane == 0) {
        const int mode = s_mode;
        const long base = (long)row * A_DIM;
        float masked[A_DIM];
        float m = -3.0e38f;
#pragma unroll
        for (int a = 0; a < A_DIM; a++) {
            const float l = acc[a] + b2[a];
            bool valid;
            if (mode == 1)      valid = ((const int*)valid_mask)[base + a] != 0;
            else if (mode == 2) valid = ((const float*)valid_mask)[base + a] != 0.0f;
            else if (mode == 0) valid = ((const unsigned char*)valid_mask)[base + a] != 0;
            else                valid = ((const unsigned short*)valid_mask)[base + a] != 0;
            masked[a] = valid ? l : -1e9f;
            m = fmaxf(m, masked[a]);
        }
        float s = 0.f;
#pragma unroll
        for (int a = 0; a < A_DIM; a++) s += expf(masked[a] - m);
        const float lse = m + logf(s);

        int pred = 0;
        float best = masked[0];
#pragma unroll
        for (int a = 1; a < A_DIM; a++)
            if (masked[a] > best) { best = masked[a]; pred = a; }

        const int gold = real_actions[row];
        const float loss = masked[gold] - lse;

        if (write_pred) {
            out[row]     = (float)pred;
            out[B + row] = loss;
        } else {
            out[row] = loss;
        }
    }
}

// ---------------------------------------------------------------- launch --
extern "C" void kernel_launch(void* const* d_in, const int* in_sizes, int n_in,
                              void* d_out, int out_size)
{
    const float* buffer_h = (const float*)d_in[0];
    const float* stack_h  = (const float*)d_in[1];
    const float* output_h = (const float*)d_in[2];
    const float* action_h = (const float*)d_in[3];
    const float* W1 = (const float*)d_in[4];
    const float* b1 = (const float*)d_in[5];
    const float* W2 = (const float*)d_in[6];
    const float* b2 = (const float*)d_in[7];
    const void* valid_mask = d_in[8];
    const int* real_actions = (const int*)d_in[9];
    float* out = (float*)d_out;

    const int B = in_sizes[0] / H_DIM;  // 16384

    const size_t totalA4 = (size_t)B * K_DIM / 4;
    splitA_kernel<<<(unsigned)((totalA4 + 255) / 256), 256>>>(buffer_h, stack_h,
                                                              output_h, action_h);
    splitB_kernel<<<dim3(H_DIM / 32, K_DIM / 32), dim3(32, 8)>>>(W1);

    const int smem1 = 2 * STAGEB;  // 192 KB
    cudaFuncSetAttribute(gemm1_fp16_kernel,
                         cudaFuncAttributeMaxDynamicSharedMemorySize, smem1);
    dim3 grid1(H_DIM / BN, B / BM);   // (4, 128)
    gemm1_fp16_kernel<<<grid1, 512, smem1>>>(b1);

    static const size_t smem2 = (size_t)A_DIM * H_DIM * sizeof(float);
    cudaFuncSetAttribute(stage2_kernel,
                         cudaFuncAttributeMaxDynamicSharedMemorySize, (int)smem2);
    const int write_pred = (out_size >= 2 * B) ? 1 : 0;
    dim3 grid2((B + 7) / 8);
    stage2_kernel<<<grid2, 256, smem2>>>(W2, b2, valid_mask, real_actions,
                                         out, B, write_pred);
}